// round 2
// baseline (speedup 1.0000x reference)
#include <cuda_runtime.h>
#include <math.h>

#define BD 8
#define NN 2048
#define DD 768
#define HH 12
#define HDI 64
#define WW 16
#define HOPP 8
#define GBB 1025
#define LBB 9
#define NWW 255

// ---------------- scratch (no allocations allowed) ----------------
__device__ float g_ctxp[BD * 8 * DD];
__device__ float g_ctx[BD * DD];
__device__ float g_hg[BD * DD];
__device__ float g_hl[BD * DD];
__device__ float g_mg[BD * HH * GBB];
__device__ float g_ml[BD * HH * LBB];

// ---------------- ctx = mean over N ----------------
__global__ __launch_bounds__(256) void ctx_part_kernel(const float* __restrict__ x) {
    int c = blockIdx.x * 256 + threadIdx.x;
    int b = blockIdx.y;
    int ch = blockIdx.z;
    const float* xp = x + ((size_t)b * NN + (size_t)ch * 256) * DD + c;
    float s = 0.f;
#pragma unroll 8
    for (int n = 0; n < 256; n++) s += xp[(size_t)n * DD];
    g_ctxp[(b * 8 + ch) * DD + c] = s;
}

__global__ __launch_bounds__(256) void ctx_fin_kernel() {
    int c = blockIdx.x * 256 + threadIdx.x;
    int b = blockIdx.y;
    float s = 0.f;
#pragma unroll
    for (int ch = 0; ch < 8; ch++) s += g_ctxp[(b * 8 + ch) * DD + c];
    g_ctx[b * DD + c] = s * (1.0f / (float)NN);
}

// ---------------- layer 1: gelu(ctx @ w1 + b1) ----------------
__global__ __launch_bounds__(128) void mlp1_kernel(const float* __restrict__ w1g,
                                                   const float* __restrict__ b1g,
                                                   const float* __restrict__ w1l,
                                                   const float* __restrict__ b1l) {
    int b = blockIdx.y;
    const float* w = blockIdx.z ? w1l : w1g;
    const float* bias = blockIdx.z ? b1l : b1g;
    float* out = blockIdx.z ? g_hl : g_hg;
    __shared__ float cs[DD];
    for (int i = threadIdx.x; i < DD; i += 128) cs[i] = g_ctx[b * DD + i];
    __syncthreads();
    int c = blockIdx.x * 128 + threadIdx.x;
    float acc = bias[c];
#pragma unroll 4
    for (int k = 0; k < DD; k++) acc += cs[k] * w[(size_t)k * DD + c];
    // exact GELU
    float ge = 0.5f * acc * (1.0f + erff(acc * 0.70710678118654752f));
    out[b * DD + c] = ge;
}

// ---------------- layer 2: tanh(h @ w2 + b2) ----------------
__global__ __launch_bounds__(128) void mlp2_kernel(const float* __restrict__ w2g,
                                                   const float* __restrict__ b2g,
                                                   const float* __restrict__ w2l,
                                                   const float* __restrict__ b2l) {
    bool isl = (blockIdx.x == 97);
    int ncol = isl ? (HH * LBB) : (HH * GBB);
    const float* w = isl ? w2l : w2g;
    const float* bias = isl ? b2l : b2g;
    const float* h = isl ? g_hl : g_hg;
    float* out = isl ? g_ml : g_mg;

    __shared__ float hs[BD * DD];
    for (int i = threadIdx.x; i < BD * DD; i += 128) hs[i] = h[i];
    __syncthreads();

    int c = isl ? threadIdx.x : blockIdx.x * 128 + threadIdx.x;
    if (c >= ncol) return;

    float acc[BD];
#pragma unroll
    for (int b = 0; b < BD; b++) acc[b] = bias[c];
    for (int k = 0; k < DD; k++) {
        float wv = w[(size_t)k * ncol + c];
#pragma unroll
        for (int b = 0; b < BD; b++) acc[b] += hs[b * DD + k] * wv;
    }
#pragma unroll
    for (int b = 0; b < BD; b++) out[b * ncol + c] = tanhf(acc[b]);
}

// ---------------- main spectral kernel ----------------
__device__ __forceinline__ float2 cmul(float2 a, float2 b) {
    return make_float2(a.x * b.x - a.y * b.y, a.x * b.y + a.y * b.x);
}

__device__ __forceinline__ float2 filt_modrelu(float2 v, float g, float bias, float prescale) {
    v.x *= prescale * g;
    v.y *= prescale * g;
    float a = sqrtf(v.x * v.x + v.y * v.y);
    float sc = fmaxf(a + bias, 0.0f) / fmaxf(a, 1e-6f);
    v.x *= sc;
    v.y *= sc;
    return v;
}

__global__ __launch_bounds__(256) void spectral_kernel(
    const float* __restrict__ x,
    const float* __restrict__ base_g, const float* __restrict__ base_l,
    const float* __restrict__ bias_g, const float* __restrict__ bias_l,
    const float* __restrict__ fusion_w,
    float* __restrict__ out) {
    __shared__ float s_time[NN];
    __shared__ float s_xl[NN];
    __shared__ float2 bufA[1024];
    __shared__ float2 bufB[1024];
    __shared__ float2 tw2[1025];   // exp(-2*pi*i*k/2048), k=0..1024
    __shared__ float2 xNyq;
    __shared__ float c16[16], s16[16], hwin[16];

    const int tid = threadIdx.x;
    const int blk = blockIdx.x;
    const int b = blk / DD;
    const int c = blk % DD;
    const int h = c >> 6;
    const float invs = 0.022097086912079608f; // 1/sqrt(2048)

    // twiddle / window tables
    for (int k = tid; k <= 1024; k += 256) {
        float ang = -(float)M_PI * (float)k * (1.0f / 1024.0f);
        float sv, cv;
        sincosf(ang, &sv, &cv);
        tw2[k] = make_float2(cv, sv);
    }
    if (tid < 16) {
        float ang = 2.0f * (float)M_PI * (float)tid * (1.0f / 16.0f);
        float sv, cv;
        sincosf(ang, &sv, &cv);
        c16[tid] = cv;
        s16[tid] = sv;
        hwin[tid] = 0.5f * (1.0f - cv);
    }

    // load row (strided over D; L2-resident)
    const float* xrow = x + (size_t)b * NN * DD + c;
    for (int n = tid; n < NN; n += 256) {
        s_time[n] = xrow[(size_t)n * DD];
        s_xl[n] = 0.0f;
    }
    __syncthreads();

    // -------- local STFT path --------
    {
        const float* mlb = g_ml + (b * HH + h) * LBB;
        const float* blb = base_l + h * LBB;
        const float* bib = bias_l + h * LBB;
        float gl[LBB], bl9[LBB];
#pragma unroll
        for (int k = 0; k < LBB; k++) {
            gl[k] = blb[k] + mlb[k];
            bl9[k] = bib[k];
        }
        for (int par = 0; par < 2; par++) {
            int nw = 2 * tid + par;
            if (nw < NWW) {
                int base = nw * HOPP;
                float t16[16];
#pragma unroll
                for (int j = 0; j < 16; j++) t16[j] = s_time[base + j] * hwin[j];
                float re[LBB], im[LBB];
#pragma unroll
                for (int k = 0; k < LBB; k++) {
                    float r = 0.f, ii = 0.f;
#pragma unroll
                    for (int j = 0; j < 16; j++) {
                        int id = (k * j) & 15;
                        r += t16[j] * c16[id];
                        ii -= t16[j] * s16[id];
                    }
                    r *= 0.25f;
                    ii *= 0.25f;
                    r *= gl[k];
                    ii *= gl[k];
                    float a = sqrtf(r * r + ii * ii);
                    float sc = fmaxf(a + bl9[k], 0.0f) / fmaxf(a, 1e-6f);
                    re[k] = r * sc;
                    im[k] = ii * sc;
                }
#pragma unroll
                for (int j = 0; j < 16; j++) {
                    float y = re[0];
#pragma unroll
                    for (int k = 1; k < 8; k++) {
                        int id = (k * j) & 15;
                        y += 2.0f * (re[k] * c16[id] - im[k] * s16[id]);
                    }
                    {
                        int id = (8 * j) & 15;
                        y += re[8] * c16[id] - im[8] * s16[id];
                    }
                    y *= 0.25f * hwin[j];
                    s_xl[base + j] += y;
                }
            }
            __syncthreads();
        }
    }

    // -------- global path: packed real FFT 2048 --------
    // pack even/odd into complex
    for (int m = tid; m < 1024; m += 256)
        bufA[m] = make_float2(s_time[2 * m], s_time[2 * m + 1]);
    __syncthreads();

    // forward Stockham FFT (1024, sign -1). src/dst ping-pong; 10 stages -> result in bufA.
    {
        float2* src = bufA;
        float2* dst = bufB;
        int ls = 1, logss = 0;
        for (int st = 0; st < 10; st++) {
            int ssm1 = (1 << logss) - 1;
#pragma unroll 2
            for (int idx = tid; idx < 512; idx += 256) {
                int q = idx & ssm1;
                int p = idx >> logss;
                float2 a = src[idx];
                float2 bb = src[idx + 512];
                float2 w = tw2[p << ls];
                int o = q + (p << (logss + 1));
                dst[o] = make_float2(a.x + bb.x, a.y + bb.y);
                float2 d = make_float2(a.x - bb.x, a.y - bb.y);
                dst[o + (1 << logss)] = cmul(d, w);
            }
            __syncthreads();
            float2* t = src; src = dst; dst = t;
            ls++; logss++;
        }
    }
    // Z = bufA. Unpack to rfft spectrum X (into bufB + xNyq), apply filter+modrelu.
    {
        const float* mgb = g_mg + (b * HH + h) * GBB;
        const float* bgb = base_g + h * GBB;
        const float* bib = bias_g + h * GBB;
        float2* Z = bufA;
        float2* X = bufB;
        for (int k = tid; k <= 512; k += 256) {
            float2 Zk = Z[k & 1023];
            float2 Zm = Z[(1024 - k) & 1023];
            float2 E = make_float2(0.5f * (Zk.x + Zm.x), 0.5f * (Zk.y - Zm.y));
            float2 O = make_float2(0.5f * (Zk.y + Zm.y), -0.5f * (Zk.x - Zm.x));
            // X[k] = E + tw2[k]*O
            float2 Xk = cmul(tw2[k], O);
            Xk.x += E.x;
            Xk.y += E.y;
            Xk = filt_modrelu(Xk, bgb[k] + mgb[k], bib[k], invs);
            if (k < 512) {
                // X[1024-k] = conj(E) + tw2[1024-k]*conj(O)
                float2 Ec = make_float2(E.x, -E.y);
                float2 Oc = make_float2(O.x, -O.y);
                float2 Xm = cmul(tw2[1024 - k], Oc);
                Xm.x += Ec.x;
                Xm.y += Ec.y;
                int kk = 1024 - k;
                Xm = filt_modrelu(Xm, bgb[kk] + mgb[kk], bib[kk], invs);
                if (k == 0) xNyq = Xm;
                else X[kk] = Xm;
            }
            X[k] = Xk;  // k==512 handled here exactly once
        }
    }
    __syncthreads();
    // Repack G[j] into bufA for inverse packed transform:
    // G[j] = (X[j]+conj(X[1024-j])) + i*conj(tw2[j])*(X[j]-conj(X[1024-j]))
    {
        float2* X = bufB;
        float2* G = bufA;
        for (int j = tid; j <= 512; j += 256) {
            float2 Xa = X[j];
            float2 Xb = (j == 0) ? xNyq : X[1024 - j];
            {
                float2 S = make_float2(Xa.x + Xb.x, Xa.y - Xb.y);
                float2 Dd = make_float2(Xa.x - Xb.x, Xa.y + Xb.y);
                float2 wc = make_float2(tw2[j].x, -tw2[j].y);
                float2 t = cmul(wc, Dd);
                G[j] = make_float2(S.x - t.y, S.y + t.x);
            }
            if (j > 0 && j < 512) {
                int jj = 1024 - j;
                float2 S = make_float2(Xb.x + Xa.x, Xb.y - Xa.y);
                float2 Dd = make_float2(Xb.x - Xa.x, Xb.y + Xa.y);
                float2 wc = make_float2(tw2[jj].x, -tw2[jj].y);
                float2 t = cmul(wc, Dd);
                G[jj] = make_float2(S.x - t.y, S.y + t.x);
            }
        }
    }
    __syncthreads();
    // inverse Stockham FFT (sign +1): result back in bufA
    {
        float2* src = bufA;
        float2* dst = bufB;
        int ls = 1, logss = 0;
        for (int st = 0; st < 10; st++) {
            int ssm1 = (1 << logss) - 1;
#pragma unroll 2
            for (int idx = tid; idx < 512; idx += 256) {
                int q = idx & ssm1;
                int p = idx >> logss;
                float2 a = src[idx];
                float2 bb = src[idx + 512];
                float2 w = tw2[p << ls];
                w.y = -w.y;  // conjugate twiddle
                int o = q + (p << (logss + 1));
                dst[o] = make_float2(a.x + bb.x, a.y + bb.y);
                float2 d = make_float2(a.x - bb.x, a.y - bb.y);
                dst[o + (1 << logss)] = cmul(d, w);
            }
            __syncthreads();
            float2* t = src; src = dst; dst = t;
            ls++; logss++;
        }
    }
    // fuse + write out (B,N,D) layout
    {
        float fw0 = fusion_w[0];
        float fw1 = fusion_w[1];
        float* orow = out + (size_t)b * NN * DD + c;
        for (int m = tid; m < 1024; m += 256) {
            float2 zc = bufA[m];
            int n0 = 2 * m;
            orow[(size_t)n0 * DD] = fw0 * (zc.x * invs) + fw1 * s_xl[n0];
            orow[(size_t)(n0 + 1) * DD] = fw0 * (zc.y * invs) + fw1 * s_xl[n0 + 1];
        }
    }
}

// ---------------- residual + layernorm ----------------
__device__ __forceinline__ float block_sum256(float v, float* red, int tid) {
#pragma unroll
    for (int o = 16; o > 0; o >>= 1) v += __shfl_xor_sync(0xffffffffu, v, o);
    if ((tid & 31) == 0) red[tid >> 5] = v;
    __syncthreads();
    if (tid < 32) {
        float t = (tid < 8) ? red[tid] : 0.0f;
#pragma unroll
        for (int o = 4; o > 0; o >>= 1) t += __shfl_xor_sync(0xffffffffu, t, o);
        if (tid == 0) red[0] = t;
    }
    __syncthreads();
    float r = red[0];
    __syncthreads();
    return r;
}

__global__ __launch_bounds__(256) void ln_kernel(const float* __restrict__ x,
                                                 const float* __restrict__ gamma,
                                                 const float* __restrict__ beta,
                                                 float* __restrict__ out) {
    __shared__ float red[32];
    int row = blockIdx.x;
    const float* xr = x + (size_t)row * DD;
    float* orow = out + (size_t)row * DD;
    int tid = threadIdx.x;

    float v0 = xr[tid] + orow[tid];
    float v1 = xr[tid + 256] + orow[tid + 256];
    float v2 = xr[tid + 512] + orow[tid + 512];

    float mu = block_sum256(v0 + v1 + v2, red, tid) * (1.0f / (float)DD);
    float d0 = v0 - mu, d1 = v1 - mu, d2 = v2 - mu;
    float var = block_sum256(d0 * d0 + d1 * d1 + d2 * d2, red, tid) * (1.0f / (float)DD);
    float rstd = rsqrtf(var + 1e-5f);

    orow[tid] = d0 * rstd * gamma[tid] + beta[tid];
    orow[tid + 256] = d1 * rstd * gamma[tid + 256] + beta[tid + 256];
    orow[tid + 512] = d2 * rstd * gamma[tid + 512] + beta[tid + 512];
}

// ---------------- launch ----------------
extern "C" void kernel_launch(void* const* d_in, const int* in_sizes, int n_in,
                              void* d_out, int out_size) {
    const float* x = (const float*)d_in[0];
    const float* bf_g = (const float*)d_in[1];
    const float* bf_l = (const float*)d_in[2];
    const float* mb_g = (const float*)d_in[3];
    const float* mb_l = (const float*)d_in[4];
    const float* w1g = (const float*)d_in[5];
    const float* b1g = (const float*)d_in[6];
    const float* w2g = (const float*)d_in[7];
    const float* b2g = (const float*)d_in[8];
    const float* w1l = (const float*)d_in[9];
    const float* b1l = (const float*)d_in[10];
    const float* w2l = (const float*)d_in[11];
    const float* b2l = (const float*)d_in[12];
    const float* fw = (const float*)d_in[13];
    const float* gamma = (const float*)d_in[14];
    const float* beta = (const float*)d_in[15];
    float* out = (float*)d_out;

    ctx_part_kernel<<<dim3(3, 8, 8), 256>>>(x);
    ctx_fin_kernel<<<dim3(3, 8), 256>>>();
    mlp1_kernel<<<dim3(6, 8, 2), 128>>>(w1g, b1g, w1l, b1l);
    mlp2_kernel<<<98, 128>>>(w2g, b2g, w2l, b2l);
    spectral_kernel<<<BD * DD, 256>>>(x, bf_g, bf_l, mb_g, mb_l, fw, out);
    ln_kernel<<<BD * NN, 256>>>(x, gamma, beta, out);
}

// round 3
// speedup vs baseline: 2.1072x; 2.1072x over previous
#include <cuda_runtime.h>
#include <math.h>

#define BD 8
#define NN 2048
#define DD 768
#define HH 12
#define GBB 1025
#define LBB 9
#define NWW 255
#define HOPP 8
#define NCG (HH * GBB)  // 12300
#define NCL (HH * LBB)  // 108

// ---------------- scratch ----------------
__device__ float g_xT[BD * DD * NN];        // (B, D, N), reused for fused output
__device__ float g_ctxp[BD * 64 * DD];
__device__ float g_ctx[BD * DD];
__device__ float g_p1[2 * 4 * BD * DD];
__device__ float g_hg[BD * DD];
__device__ float g_hl[BD * DD];
__device__ float g_pg[8 * BD * NCG];
__device__ float g_pl[8 * BD * NCL];
__device__ float g_mg[BD * NCG];
__device__ float g_ml[BD * NCL];
__device__ float2 g_tw[1025];               // exp(-i*pi*k/1024)

__device__ __forceinline__ float2 cmul(float2 a, float2 b) {
    return make_float2(a.x * b.x - a.y * b.y, a.x * b.y + a.y * b.x);
}

// ---------------- init: twiddle table ----------------
__global__ __launch_bounds__(256) void init_kernel() {
    int k = blockIdx.x * 256 + threadIdx.x;
    if (k <= 1024) {
        float ang = -(float)M_PI * (float)k * (1.0f / 1024.0f);
        float sv, cv;
        sincosf(ang, &sv, &cv);
        g_tw[k] = make_float2(cv, sv);
    }
}

// ---------------- transpose in: x(B,N,D) -> g_xT(B,D,N), + ctx partials ----------------
__global__ __launch_bounds__(256) void tr_in_kernel(const float* __restrict__ x) {
    __shared__ float tile[32][33];
    __shared__ float red[8][32];
    int b = blockIdx.z;
    int d0 = blockIdx.x * 32;
    int n0 = blockIdx.y * 32;
    int tx = threadIdx.x, ty = threadIdx.y;

    const float* xp = x + ((size_t)(b * NN + n0 + ty)) * DD + d0 + tx;
    float p = 0.f;
#pragma unroll
    for (int i = 0; i < 4; i++) {
        float v = xp[(size_t)i * 8 * DD];
        tile[ty + 8 * i][tx] = v;
        p += v;
    }
    red[ty][tx] = p;
    __syncthreads();
    if (ty == 0) {
        float s = 0.f;
#pragma unroll
        for (int j = 0; j < 8; j++) s += red[j][tx];
        g_ctxp[(size_t)(b * 64 + blockIdx.y) * DD + d0 + tx] = s;
    }
    float* op = g_xT + ((size_t)(b * DD + d0 + ty)) * NN + n0 + tx;
#pragma unroll
    for (int i = 0; i < 4; i++) op[(size_t)i * 8 * NN] = tile[tx][ty + 8 * i];
}

__global__ __launch_bounds__(256) void ctx_fin_kernel() {
    int idx = blockIdx.x * 256 + threadIdx.x;  // over BD*DD = 6144
    int b = idx / DD;
    int d = idx - b * DD;
    const float* pp = g_ctxp + (size_t)b * 64 * DD + d;
    float s = 0.f;
#pragma unroll 8
    for (int ny = 0; ny < 64; ny++) s += pp[(size_t)ny * DD];
    g_ctx[idx] = s * (1.0f / (float)NN);
}

// ---------------- mlp layer 1 (split-K partials) ----------------
__global__ __launch_bounds__(128) void mlp1_part_kernel(const float* __restrict__ w1g,
                                                        const float* __restrict__ w1l) {
    int cb = blockIdx.x % 6;
    int ks = blockIdx.x / 6;
    int b = blockIdx.y;
    int z = blockIdx.z;
    const float* w = z ? w1l : w1g;
    __shared__ float cs[192];
    int k0 = ks * 192;
    for (int i = threadIdx.x; i < 192; i += 128) cs[i] = g_ctx[b * DD + k0 + i];
    __syncthreads();
    int c = cb * 128 + threadIdx.x;
    const float* wp = w + (size_t)k0 * DD + c;
    float acc = 0.f;
#pragma unroll 8
    for (int kk = 0; kk < 192; kk++) acc += cs[kk] * wp[(size_t)kk * DD];
    g_p1[((z * 4 + ks) * BD + b) * DD + c] = acc;
}

__global__ __launch_bounds__(128) void mlp1_fin_kernel(const float* __restrict__ b1g,
                                                       const float* __restrict__ b1l) {
    int c = blockIdx.x * 128 + threadIdx.x;
    int b = blockIdx.y;
    int z = blockIdx.z;
    const float* bias = z ? b1l : b1g;
    float* out = z ? g_hl : g_hg;
    float s = bias[c];
#pragma unroll
    for (int ks = 0; ks < 4; ks++) s += g_p1[((z * 4 + ks) * BD + b) * DD + c];
    out[b * DD + c] = 0.5f * s * (1.0f + erff(s * 0.70710678118654752f));
}

// ---------------- mlp layer 2 (split-K partials) ----------------
__global__ __launch_bounds__(128) void mlp2_part_kernel(const float* __restrict__ w2g,
                                                        const float* __restrict__ w2l) {
    bool isl = (blockIdx.x == 97);
    int by = blockIdx.y;      // k-chunk
    int k0 = by * 96;
    __shared__ float hs[BD * 96];
    const float* h = isl ? g_hl : g_hg;
    for (int i = threadIdx.x; i < BD * 96; i += 128) {
        int b = i / 96, kk = i - b * 96;
        hs[i] = h[b * DD + k0 + kk];
    }
    __syncthreads();
    int ncol = isl ? NCL : NCG;
    int c = isl ? threadIdx.x : blockIdx.x * 128 + threadIdx.x;
    if (c >= ncol) return;
    const float* w = isl ? w2l : w2g;
    float* pp = isl ? g_pl : g_pg;
    float acc[BD];
#pragma unroll
    for (int b = 0; b < BD; b++) acc[b] = 0.f;
    const float* wp = w + (size_t)k0 * ncol + c;
#pragma unroll 4
    for (int kk = 0; kk < 96; kk++) {
        float wv = wp[(size_t)kk * ncol];
#pragma unroll
        for (int b = 0; b < BD; b++) acc[b] += hs[b * 96 + kk] * wv;
    }
#pragma unroll
    for (int b = 0; b < BD; b++) pp[(size_t)(by * BD + b) * ncol + c] = acc[b];
}

__global__ __launch_bounds__(128) void mlp2_fin_kernel(const float* __restrict__ b2g,
                                                       const float* __restrict__ b2l) {
    bool isl = (blockIdx.x == 97);
    int ncol = isl ? NCL : NCG;
    int c = isl ? threadIdx.x : blockIdx.x * 128 + threadIdx.x;
    if (c >= ncol) return;
    int b = blockIdx.y;
    const float* bias = isl ? b2l : b2g;
    const float* pp = isl ? g_pl : g_pg;
    float* out = isl ? g_ml : g_mg;
    float s = bias[c];
#pragma unroll
    for (int ks = 0; ks < 8; ks++) s += pp[(size_t)(ks * BD + b) * ncol + c];
    out[(size_t)b * ncol + c] = tanhf(s);
}

// ---------------- radix-4 Stockham FFT (1024 pts, 5 stages) ----------------
template <bool INV>
__device__ __forceinline__ void fft1024(float2* src, float2* dst, const float2* tws, int tid) {
#pragma unroll
    for (int t = 0; t < 5; t++) {
        const int s = 1 << (2 * t);
        int q = tid & (s - 1);
        int ps = tid - q;
        float2 a = src[tid];
        float2 b = src[tid + 256];
        float2 c = src[tid + 512];
        float2 d = src[tid + 768];
        float2 w1 = tws[2 * ps];
        float2 w2 = tws[4 * ps];
        if (INV) { w1.y = -w1.y; w2.y = -w2.y; }
        float2 w3 = cmul(w1, w2);
        float2 apc = make_float2(a.x + c.x, a.y + c.y);
        float2 amc = make_float2(a.x - c.x, a.y - c.y);
        float2 bpd = make_float2(b.x + d.x, b.y + d.y);
        float2 bmd = make_float2(b.x - d.x, b.y - d.y);
        int o = 4 * tid - 3 * q;
        dst[o] = make_float2(apc.x + bpd.x, apc.y + bpd.y);
        float2 t1, t3;
        if (!INV) {
            t1 = make_float2(amc.x + bmd.y, amc.y - bmd.x);
            t3 = make_float2(amc.x - bmd.y, amc.y + bmd.x);
        } else {
            t1 = make_float2(amc.x - bmd.y, amc.y + bmd.x);
            t3 = make_float2(amc.x + bmd.y, amc.y - bmd.x);
        }
        dst[o + s] = cmul(t1, w1);
        dst[o + 2 * s] = cmul(make_float2(apc.x - bpd.x, apc.y - bpd.y), w2);
        dst[o + 3 * s] = cmul(t3, w3);
        __syncthreads();
        float2* tmp = src; src = dst; dst = tmp;
    }
}

__device__ __forceinline__ float2 filt_modrelu(float2 v, float g, float bias, float prescale) {
    v.x *= prescale * g;
    v.y *= prescale * g;
    float a = sqrtf(v.x * v.x + v.y * v.y);
    float sc = fmaxf(a + bias, 0.0f) / fmaxf(a, 1e-6f);
    v.x *= sc;
    v.y *= sc;
    return v;
}

__global__ __launch_bounds__(256) void spectral_kernel(
    const float* __restrict__ base_g, const float* __restrict__ base_l,
    const float* __restrict__ bias_g, const float* __restrict__ bias_l,
    const float* __restrict__ fusion_w) {
    __shared__ float2 bufA[1024];
    __shared__ float2 bufB[1024];   // aliased with s_time
    __shared__ float s_xl[2048];
    __shared__ float2 tws[1025];
    __shared__ float2 xNyq;
    float* s_time = (float*)bufB;

    const int tid = threadIdx.x;
    const int blk = blockIdx.x;
    const int b = blk / DD;
    const int c = blk - b * DD;
    const int h = c >> 6;
    const float invs = 0.022097086912079608f;  // 1/sqrt(2048)

    for (int k = tid; k <= 1024; k += 256) tws[k] = g_tw[k];

    float* row = g_xT + (size_t)blk * NN;
    {
        const float4* src4 = (const float4*)row;
        float4* dst4 = (float4*)s_time;
        for (int i = tid; i < 512; i += 256) dst4[i] = src4[i];
        for (int n = tid; n < 2048; n += 256) s_xl[n] = 0.f;
    }
    __syncthreads();

    // -------- local STFT path --------
    {
        const float c16[16] = {1.f, 0.92387953251128674f, 0.70710678118654752f, 0.38268343236508977f,
                               0.f, -0.38268343236508977f, -0.70710678118654752f, -0.92387953251128674f,
                               -1.f, -0.92387953251128674f, -0.70710678118654752f, -0.38268343236508977f,
                               0.f, 0.38268343236508977f, 0.70710678118654752f, 0.92387953251128674f};
        const float s16[16] = {0.f, 0.38268343236508977f, 0.70710678118654752f, 0.92387953251128674f,
                               1.f, 0.92387953251128674f, 0.70710678118654752f, 0.38268343236508977f,
                               0.f, -0.38268343236508977f, -0.70710678118654752f, -0.92387953251128674f,
                               -1.f, -0.92387953251128674f, -0.70710678118654752f, -0.38268343236508977f};
        const float hwin[16] = {0.f, 0.03806023374435663f, 0.14644660940672624f, 0.30865828381745508f,
                                0.5f, 0.69134171618254492f, 0.85355339059327376f, 0.96193976625564337f,
                                1.f, 0.96193976625564337f, 0.85355339059327376f, 0.69134171618254492f,
                                0.5f, 0.30865828381745508f, 0.14644660940672624f, 0.03806023374435663f};
        const float* mlb = g_ml + (b * HH + h) * LBB;
        const float* blb = base_l + h * LBB;
        const float* bib = bias_l + h * LBB;
        float gl[LBB], bl9[LBB];
#pragma unroll
        for (int k = 0; k < LBB; k++) {
            gl[k] = blb[k] + mlb[k];
            bl9[k] = bib[k];
        }
        for (int par = 0; par < 2; par++) {
            int nw = 2 * tid + par;
            if (nw < NWW) {
                int base = nw * HOPP;
                float t16[16];
#pragma unroll
                for (int j = 0; j < 16; j++) t16[j] = s_time[base + j] * hwin[j];
                float re[LBB], im[LBB];
#pragma unroll
                for (int k = 0; k < LBB; k++) {
                    float r = 0.f, ii = 0.f;
#pragma unroll
                    for (int j = 0; j < 16; j++) {
                        int id = (k * j) & 15;
                        r += t16[j] * c16[id];
                        ii -= t16[j] * s16[id];
                    }
                    r *= 0.25f;
                    ii *= 0.25f;
                    r *= gl[k];
                    ii *= gl[k];
                    float a = sqrtf(r * r + ii * ii);
                    float sc = fmaxf(a + bl9[k], 0.0f) / fmaxf(a, 1e-6f);
                    re[k] = r * sc;
                    im[k] = ii * sc;
                }
#pragma unroll
                for (int j = 0; j < 16; j++) {
                    float y = re[0];
#pragma unroll
                    for (int k = 1; k < 8; k++) {
                        int id = (k * j) & 15;
                        y += 2.0f * (re[k] * c16[id] - im[k] * s16[id]);
                    }
                    {
                        int id = (8 * j) & 15;
                        y += re[8] * c16[id] - im[8] * s16[id];
                    }
                    y *= 0.25f * hwin[j];
                    s_xl[base + j] += y;
                }
            }
            __syncthreads();
        }
    }

    // -------- global path --------
    // pack even/odd (s_time == bufB, so pack into bufA BEFORE fft touches bufB)
    for (int m = tid; m < 1024; m += 256)
        bufA[m] = make_float2(s_time[2 * m], s_time[2 * m + 1]);
    __syncthreads();

    fft1024<false>(bufA, bufB, tws, tid);  // 5 stages: result lands in bufB

    // unpack Z(bufB) -> rfft spectrum X(bufA) + filter + modrelu
    {
        const float* mgb = g_mg + (b * HH + h) * GBB;
        const float* bgb = base_g + h * GBB;
        const float* bib = bias_g + h * GBB;
        float2* Z = bufB;
        float2* X = bufA;
        for (int k = tid; k <= 512; k += 256) {
            float2 Zk = Z[k & 1023];
            float2 Zm = Z[(1024 - k) & 1023];
            float2 E = make_float2(0.5f * (Zk.x + Zm.x), 0.5f * (Zk.y - Zm.y));
            float2 O = make_float2(0.5f * (Zk.y + Zm.y), -0.5f * (Zk.x - Zm.x));
            float2 Xk = cmul(tws[k], O);
            Xk.x += E.x;
            Xk.y += E.y;
            Xk = filt_modrelu(Xk, bgb[k] + mgb[k], bib[k], invs);
            if (k < 512) {
                float2 Ec = make_float2(E.x, -E.y);
                float2 Oc = make_float2(O.x, -O.y);
                float2 Xm = cmul(tws[1024 - k], Oc);
                Xm.x += Ec.x;
                Xm.y += Ec.y;
                int kk = 1024 - k;
                Xm = filt_modrelu(Xm, bgb[kk] + mgb[kk], bib[kk], invs);
                if (k == 0) xNyq = Xm;
                else X[kk] = Xm;
            }
            X[k] = Xk;
        }
    }
    __syncthreads();

    // repack X(bufA) -> G(bufB)
    {
        float2* X = bufA;
        float2* G = bufB;
        for (int j = tid; j <= 512; j += 256) {
            float2 Xa = X[j];
            float2 Xb = (j == 0) ? xNyq : X[1024 - j];
            {
                float2 S = make_float2(Xa.x + Xb.x, Xa.y - Xb.y);
                float2 Dd = make_float2(Xa.x - Xb.x, Xa.y + Xb.y);
                float2 wc = make_float2(tws[j].x, -tws[j].y);
                float2 t = cmul(wc, Dd);
                G[j] = make_float2(S.x - t.y, S.y + t.x);
            }
            if (j > 0 && j < 512) {
                int jj = 1024 - j;
                float2 S = make_float2(Xb.x + Xa.x, Xb.y - Xa.y);
                float2 Dd = make_float2(Xb.x - Xa.x, Xb.y + Xa.y);
                float2 wc = make_float2(tws[jj].x, -tws[jj].y);
                float2 t = cmul(wc, Dd);
                G[jj] = make_float2(S.x - t.y, S.y + t.x);
            }
        }
    }
    __syncthreads();

    fft1024<true>(bufB, bufA, tws, tid);  // inverse: result lands in bufA

    // fuse + contiguous write back into g_xT
    {
        float fw0 = fusion_w[0];
        float fw1 = fusion_w[1];
        float2* orow2 = (float2*)row;
        float2* xl2 = (float2*)s_xl;
        for (int m = tid; m < 1024; m += 256) {
            float2 zc = bufA[m];
            float2 xl = xl2[m];
            orow2[m] = make_float2(fw0 * (zc.x * invs) + fw1 * xl.x,
                                   fw0 * (zc.y * invs) + fw1 * xl.y);
        }
    }
}

// ---------------- transpose out: g_xT(B,D,N) -> out(B,N,D) ----------------
__global__ __launch_bounds__(256) void tr_out_kernel(float* __restrict__ out) {
    __shared__ float tile[32][33];
    int b = blockIdx.z;
    int n0 = blockIdx.x * 32;
    int d0 = blockIdx.y * 32;
    int tx = threadIdx.x, ty = threadIdx.y;
    const float* ip = g_xT + ((size_t)(b * DD + d0 + ty)) * NN + n0 + tx;
#pragma unroll
    for (int i = 0; i < 4; i++) tile[ty + 8 * i][tx] = ip[(size_t)i * 8 * NN];
    __syncthreads();
    float* op = out + ((size_t)(b * NN + n0 + ty)) * DD + d0 + tx;
#pragma unroll
    for (int i = 0; i < 4; i++) op[(size_t)i * 8 * DD] = tile[tx][ty + 8 * i];
}

// ---------------- residual + layernorm ----------------
__device__ __forceinline__ float block_sum256(float v, float* red, int tid) {
#pragma unroll
    for (int o = 16; o > 0; o >>= 1) v += __shfl_xor_sync(0xffffffffu, v, o);
    if ((tid & 31) == 0) red[tid >> 5] = v;
    __syncthreads();
    if (tid < 32) {
        float t = (tid < 8) ? red[tid] : 0.0f;
#pragma unroll
        for (int o = 4; o > 0; o >>= 1) t += __shfl_xor_sync(0xffffffffu, t, o);
        if (tid == 0) red[0] = t;
    }
    __syncthreads();
    float r = red[0];
    __syncthreads();
    return r;
}

__global__ __launch_bounds__(256) void ln_kernel(const float* __restrict__ x,
                                                 const float* __restrict__ gamma,
                                                 const float* __restrict__ beta,
                                                 float* __restrict__ out) {
    __shared__ float red[32];
    int row = blockIdx.x;
    const float* xr = x + (size_t)row * DD;
    float* orow = out + (size_t)row * DD;
    int tid = threadIdx.x;

    float v0 = xr[tid] + orow[tid];
    float v1 = xr[tid + 256] + orow[tid + 256];
    float v2 = xr[tid + 512] + orow[tid + 512];

    float mu = block_sum256(v0 + v1 + v2, red, tid) * (1.0f / (float)DD);
    float d0 = v0 - mu, d1 = v1 - mu, d2 = v2 - mu;
    float var = block_sum256(d0 * d0 + d1 * d1 + d2 * d2, red, tid) * (1.0f / (float)DD);
    float rstd = rsqrtf(var + 1e-5f);

    orow[tid] = d0 * rstd * gamma[tid] + beta[tid];
    orow[tid + 256] = d1 * rstd * gamma[tid + 256] + beta[tid + 256];
    orow[tid + 512] = d2 * rstd * gamma[tid + 512] + beta[tid + 512];
}

// ---------------- launch ----------------
extern "C" void kernel_launch(void* const* d_in, const int* in_sizes, int n_in,
                              void* d_out, int out_size) {
    const float* x = (const float*)d_in[0];
    const float* bf_g = (const float*)d_in[1];
    const float* bf_l = (const float*)d_in[2];
    const float* mb_g = (const float*)d_in[3];
    const float* mb_l = (const float*)d_in[4];
    const float* w1g = (const float*)d_in[5];
    const float* b1g = (const float*)d_in[6];
    const float* w2g = (const float*)d_in[7];
    const float* b2g = (const float*)d_in[8];
    const float* w1l = (const float*)d_in[9];
    const float* b1l = (const float*)d_in[10];
    const float* w2l = (const float*)d_in[11];
    const float* b2l = (const float*)d_in[12];
    const float* fw = (const float*)d_in[13];
    const float* gamma = (const float*)d_in[14];
    const float* beta = (const float*)d_in[15];
    float* out = (float*)d_out;

    init_kernel<<<5, 256>>>();
    tr_in_kernel<<<dim3(24, 64, 8), dim3(32, 8)>>>(x);
    ctx_fin_kernel<<<24, 256>>>();
    mlp1_part_kernel<<<dim3(24, 8, 2), 128>>>(w1g, w1l);
    mlp1_fin_kernel<<<dim3(6, 8, 2), 128>>>(b1g, b1l);
    mlp2_part_kernel<<<dim3(98, 8), 128>>>(w2g, w2l);
    mlp2_fin_kernel<<<dim3(98, 8), 128>>>(b2g, b2l);
    spectral_kernel<<<BD * DD, 256>>>(bf_g, bf_l, mb_g, mb_l, fw);
    tr_out_kernel<<<dim3(64, 24, 8), dim3(32, 8)>>>(out);
    ln_kernel<<<BD * NN, 256>>>(x, gamma, beta, out);
}

// round 4
// speedup vs baseline: 2.6046x; 1.2361x over previous
#include <cuda_runtime.h>
#include <math.h>

#define BD 8
#define NN 2048
#define DD 768
#define HH 12
#define GBB 1025
#define LBB 9
#define NWW 255
#define HOPP 8
#define NCG (HH * GBB)  // 12300
#define NCL (HH * LBB)  // 108
#define PADI(n) ((n) + ((n) >> 4))

// ---------------- scratch ----------------
__device__ float g_xT[BD * DD * NN];        // (B, D, N), reused for fused output
__device__ float g_ctxp[BD * 64 * DD];
__device__ float g_ctx[BD * DD];
__device__ float g_p1[2 * 12 * BD * DD];
__device__ float g_hg[BD * DD];
__device__ float g_hl[BD * DD];
__device__ float g_pg[8 * BD * NCG];
__device__ float g_pl[8 * BD * NCL];
__device__ float g_mg[BD * NCG];
__device__ float g_ml[BD * NCL];
__device__ float2 g_tw[1025];               // exp(-i*pi*k/1024)

__device__ __forceinline__ float2 cmul(float2 a, float2 b) {
    return make_float2(a.x * b.x - a.y * b.y, a.x * b.y + a.y * b.x);
}

// ---------------- init: twiddle table ----------------
__global__ __launch_bounds__(256) void init_kernel() {
    int k = blockIdx.x * 256 + threadIdx.x;
    if (k <= 1024) {
        float ang = -(float)M_PI * (float)k * (1.0f / 1024.0f);
        float sv, cv;
        sincosf(ang, &sv, &cv);
        g_tw[k] = make_float2(cv, sv);
    }
}

// ---------------- transpose in: x(B,N,D) -> g_xT(B,D,N), + ctx partials ----------------
__global__ __launch_bounds__(256) void tr_in_kernel(const float* __restrict__ x) {
    __shared__ float tile[32][33];
    __shared__ float red[8][32];
    int b = blockIdx.z;
    int d0 = blockIdx.x * 32;
    int n0 = blockIdx.y * 32;
    int tx = threadIdx.x, ty = threadIdx.y;

    const float* xp = x + ((size_t)(b * NN + n0 + ty)) * DD + d0 + tx;
    float p = 0.f;
#pragma unroll
    for (int i = 0; i < 4; i++) {
        float v = xp[(size_t)i * 8 * DD];
        tile[ty + 8 * i][tx] = v;
        p += v;
    }
    red[ty][tx] = p;
    __syncthreads();
    if (ty == 0) {
        float s = 0.f;
#pragma unroll
        for (int j = 0; j < 8; j++) s += red[j][tx];
        g_ctxp[(size_t)(b * 64 + blockIdx.y) * DD + d0 + tx] = s;
    }
    float* op = g_xT + ((size_t)(b * DD + d0 + ty)) * NN + n0 + tx;
#pragma unroll
    for (int i = 0; i < 4; i++) op[(size_t)i * 8 * NN] = tile[tx][ty + 8 * i];
}

__global__ __launch_bounds__(256) void ctx_fin_kernel() {
    int idx = blockIdx.x * 256 + threadIdx.x;  // over BD*DD = 6144
    int b = idx / DD;
    int d = idx - b * DD;
    const float* pp = g_ctxp + (size_t)b * 64 * DD + d;
    float s = 0.f;
#pragma unroll 8
    for (int ny = 0; ny < 64; ny++) s += pp[(size_t)ny * DD];
    g_ctx[idx] = s * (1.0f / (float)NN);
}

// ---------------- mlp layer 1 (split-K partials, 12 chunks of 64) ----------------
__global__ __launch_bounds__(128) void mlp1_part_kernel(const float* __restrict__ w1g,
                                                        const float* __restrict__ w1l) {
    int cb = blockIdx.x % 6;
    int ks = blockIdx.x / 6;   // 0..11
    int b = blockIdx.y;
    int z = blockIdx.z;
    const float* w = z ? w1l : w1g;
    __shared__ float cs[64];
    int k0 = ks * 64;
    if (threadIdx.x < 64) cs[threadIdx.x] = g_ctx[b * DD + k0 + threadIdx.x];
    __syncthreads();
    int c = cb * 128 + threadIdx.x;
    const float* wp = w + (size_t)k0 * DD + c;
    float acc = 0.f;
#pragma unroll 8
    for (int kk = 0; kk < 64; kk++) acc += cs[kk] * wp[(size_t)kk * DD];
    g_p1[((z * 12 + ks) * BD + b) * DD + c] = acc;
}

__global__ __launch_bounds__(128) void mlp1_fin_kernel(const float* __restrict__ b1g,
                                                       const float* __restrict__ b1l) {
    int c = blockIdx.x * 128 + threadIdx.x;
    int b = blockIdx.y;
    int z = blockIdx.z;
    const float* bias = z ? b1l : b1g;
    float* out = z ? g_hl : g_hg;
    float s = bias[c];
#pragma unroll
    for (int ks = 0; ks < 12; ks++) s += g_p1[((z * 12 + ks) * BD + b) * DD + c];
    out[b * DD + c] = 0.5f * s * (1.0f + erff(s * 0.70710678118654752f));
}

// ---------------- mlp layer 2 (split-K partials) ----------------
__global__ __launch_bounds__(128) void mlp2_part_kernel(const float* __restrict__ w2g,
                                                        const float* __restrict__ w2l) {
    bool isl = (blockIdx.x == 97);
    int by = blockIdx.y;      // k-chunk
    int k0 = by * 96;
    __shared__ float hs[BD * 96];
    const float* h = isl ? g_hl : g_hg;
    for (int i = threadIdx.x; i < BD * 96; i += 128) {
        int b = i / 96, kk = i - b * 96;
        hs[i] = h[b * DD + k0 + kk];
    }
    __syncthreads();
    int ncol = isl ? NCL : NCG;
    int c = isl ? threadIdx.x : blockIdx.x * 128 + threadIdx.x;
    if (c >= ncol) return;
    const float* w = isl ? w2l : w2g;
    float* pp = isl ? g_pl : g_pg;
    float acc[BD];
#pragma unroll
    for (int b = 0; b < BD; b++) acc[b] = 0.f;
    const float* wp = w + (size_t)k0 * ncol + c;
#pragma unroll 4
    for (int kk = 0; kk < 96; kk++) {
        float wv = wp[(size_t)kk * ncol];
#pragma unroll
        for (int b = 0; b < BD; b++) acc[b] += hs[b * 96 + kk] * wv;
    }
#pragma unroll
    for (int b = 0; b < BD; b++) pp[(size_t)(by * BD + b) * ncol + c] = acc[b];
}

__global__ __launch_bounds__(128) void mlp2_fin_kernel(const float* __restrict__ b2g,
                                                       const float* __restrict__ b2l) {
    bool isl = (blockIdx.x == 97);
    int ncol = isl ? NCL : NCG;
    int c = isl ? threadIdx.x : blockIdx.x * 128 + threadIdx.x;
    if (c >= ncol) return;
    int b = blockIdx.y;
    const float* bias = isl ? b2l : b2g;
    const float* pp = isl ? g_pl : g_pg;
    float* out = isl ? g_ml : g_mg;
    float s = bias[c];
#pragma unroll
    for (int ks = 0; ks < 8; ks++) s += pp[(size_t)(ks * BD + b) * ncol + c];
    out[(size_t)b * ncol + c] = tanhf(s);
}

// ---------------- radix-4 Stockham FFT (1024 pts, 5 stages) ----------------
template <bool INV>
__device__ __forceinline__ void fft1024(float2* src, float2* dst, const float2* tws, int tid) {
#pragma unroll
    for (int t = 0; t < 5; t++) {
        const int s = 1 << (2 * t);
        int q = tid & (s - 1);
        int ps = tid - q;
        float2 a = src[tid];
        float2 b = src[tid + 256];
        float2 c = src[tid + 512];
        float2 d = src[tid + 768];
        float2 w1 = tws[2 * ps];
        float2 w2 = tws[4 * ps];
        if (INV) { w1.y = -w1.y; w2.y = -w2.y; }
        float2 w3 = cmul(w1, w2);
        float2 apc = make_float2(a.x + c.x, a.y + c.y);
        float2 amc = make_float2(a.x - c.x, a.y - c.y);
        float2 bpd = make_float2(b.x + d.x, b.y + d.y);
        float2 bmd = make_float2(b.x - d.x, b.y - d.y);
        int o = 4 * tid - 3 * q;
        dst[o] = make_float2(apc.x + bpd.x, apc.y + bpd.y);
        float2 t1, t3;
        if (!INV) {
            t1 = make_float2(amc.x + bmd.y, amc.y - bmd.x);
            t3 = make_float2(amc.x - bmd.y, amc.y + bmd.x);
        } else {
            t1 = make_float2(amc.x - bmd.y, amc.y + bmd.x);
            t3 = make_float2(amc.x + bmd.y, amc.y - bmd.x);
        }
        dst[o + s] = cmul(t1, w1);
        dst[o + 2 * s] = cmul(make_float2(apc.x - bpd.x, apc.y - bpd.y), w2);
        dst[o + 3 * s] = cmul(t3, w3);
        __syncthreads();
        float2* tmp = src; src = dst; dst = tmp;
    }
}

__device__ __forceinline__ float2 filt_modrelu(float2 v, float g, float bias, float prescale) {
    v.x *= prescale * g;
    v.y *= prescale * g;
    float a = sqrtf(v.x * v.x + v.y * v.y);
    float sc = fmaxf(a + bias, 0.0f) / fmaxf(a, 1e-6f);
    v.x *= sc;
    v.y *= sc;
    return v;
}

__global__ __launch_bounds__(256) void spectral_kernel(
    const float* __restrict__ base_g, const float* __restrict__ base_l,
    const float* __restrict__ bias_g, const float* __restrict__ bias_l,
    const float* __restrict__ fusion_w) {
    __shared__ float2 bufA[1024];
    __shared__ float2 uB[1088];        // union: padded s_time (2176 floats) / bufB (1024 float2)
    __shared__ float s_xl[2176];       // padded overlap-add accumulator
    __shared__ float2 tws[1025];
    __shared__ float2 xNyq;
    float2* bufB = uB;
    float* s_time = (float*)uB;

    const int tid = threadIdx.x;
    const int blk = blockIdx.x;
    const int b = blk / DD;
    const int c = blk - b * DD;
    const int h = c >> 6;
    const float invs = 0.022097086912079608f;  // 1/sqrt(2048)

    for (int k = tid; k <= 1024; k += 256) tws[k] = g_tw[k];

    float* row = g_xT + (size_t)blk * NN;
    {
        const float4* src4 = (const float4*)row;
        for (int i = tid; i < 512; i += 256) {
            float4 v = src4[i];
            int p = PADI(4 * i);   // 4i..4i+3 stay inside one 16-group
            s_time[p] = v.x;
            s_time[p + 1] = v.y;
            s_time[p + 2] = v.z;
            s_time[p + 3] = v.w;
        }
        for (int n = tid; n < 2176; n += 256) s_xl[n] = 0.f;
    }
    __syncthreads();

    // -------- local STFT path (padded SMEM, conflict-free; j=0 skipped: hann(0)=0) ----
    {
        const float c16[16] = {1.f, 0.92387953251128674f, 0.70710678118654752f, 0.38268343236508977f,
                               0.f, -0.38268343236508977f, -0.70710678118654752f, -0.92387953251128674f,
                               -1.f, -0.92387953251128674f, -0.70710678118654752f, -0.38268343236508977f,
                               0.f, 0.38268343236508977f, 0.70710678118654752f, 0.92387953251128674f};
        const float s16[16] = {0.f, 0.38268343236508977f, 0.70710678118654752f, 0.92387953251128674f,
                               1.f, 0.92387953251128674f, 0.70710678118654752f, 0.38268343236508977f,
                               0.f, -0.38268343236508977f, -0.70710678118654752f, -0.92387953251128674f,
                               -1.f, -0.92387953251128674f, -0.70710678118654752f, -0.38268343236508977f};
        const float hwin[16] = {0.f, 0.03806023374435663f, 0.14644660940672624f, 0.30865828381745508f,
                                0.5f, 0.69134171618254492f, 0.85355339059327376f, 0.96193976625564337f,
                                1.f, 0.96193976625564337f, 0.85355339059327376f, 0.69134171618254492f,
                                0.5f, 0.30865828381745508f, 0.14644660940672624f, 0.03806023374435663f};
        const float* mlb = g_ml + (b * HH + h) * LBB;
        const float* blb = base_l + h * LBB;
        const float* bib = bias_l + h * LBB;
        float gl[LBB], bl9[LBB];
#pragma unroll
        for (int k = 0; k < LBB; k++) {
            gl[k] = blb[k] + mlb[k];
            bl9[k] = bib[k];
        }
        for (int par = 0; par < 2; par++) {
            int nw = 2 * tid + par;
            if (nw < NWW) {
                int base = nw * HOPP;
                float t16[16];
#pragma unroll
                for (int j = 1; j < 16; j++) t16[j] = s_time[PADI(base + j)] * hwin[j];
                float re[LBB], im[LBB];
#pragma unroll
                for (int k = 0; k < LBB; k++) {
                    float r = 0.f, ii = 0.f;
#pragma unroll
                    for (int j = 1; j < 16; j++) {
                        int id = (k * j) & 15;
                        r += t16[j] * c16[id];
                        ii -= t16[j] * s16[id];
                    }
                    r *= 0.25f;
                    ii *= 0.25f;
                    r *= gl[k];
                    ii *= gl[k];
                    float a = sqrtf(r * r + ii * ii);
                    float sc = fmaxf(a + bl9[k], 0.0f) / fmaxf(a, 1e-6f);
                    re[k] = r * sc;
                    im[k] = ii * sc;
                }
#pragma unroll
                for (int j = 1; j < 16; j++) {
                    float y = re[0];
#pragma unroll
                    for (int k = 1; k < 8; k++) {
                        int id = (k * j) & 15;
                        y += 2.0f * (re[k] * c16[id] - im[k] * s16[id]);
                    }
                    {
                        int id = (8 * j) & 15;
                        y += re[8] * c16[id] - im[8] * s16[id];
                    }
                    y *= 0.25f * hwin[j];
                    s_xl[PADI(base + j)] += y;
                }
            }
            __syncthreads();
        }
    }

    // -------- global path --------
    // pack even/odd into bufA (s_time aliases bufB; dead after this)
    for (int m = tid; m < 1024; m += 256) {
        int p = PADI(2 * m);  // 2m, 2m+1 share a 16-group
        bufA[m] = make_float2(s_time[p], s_time[p + 1]);
    }
    __syncthreads();

    fft1024<false>(bufA, bufB, tws, tid);  // result in bufB

    // unpack Z(bufB) -> rfft spectrum X(bufA) + filter + modrelu
    {
        const float* mgb = g_mg + (b * HH + h) * GBB;
        const float* bgb = base_g + h * GBB;
        const float* bib = bias_g + h * GBB;
        float2* Z = bufB;
        float2* X = bufA;
        for (int k = tid; k <= 512; k += 256) {
            float2 Zk = Z[k & 1023];
            float2 Zm = Z[(1024 - k) & 1023];
            float2 E = make_float2(0.5f * (Zk.x + Zm.x), 0.5f * (Zk.y - Zm.y));
            float2 O = make_float2(0.5f * (Zk.y + Zm.y), -0.5f * (Zk.x - Zm.x));
            float2 Xk = cmul(tws[k], O);
            Xk.x += E.x;
            Xk.y += E.y;
            Xk = filt_modrelu(Xk, bgb[k] + mgb[k], bib[k], invs);
            if (k < 512) {
                float2 Ec = make_float2(E.x, -E.y);
                float2 Oc = make_float2(O.x, -O.y);
                float2 Xm = cmul(tws[1024 - k], Oc);
                Xm.x += Ec.x;
                Xm.y += Ec.y;
                int kk = 1024 - k;
                Xm = filt_modrelu(Xm, bgb[kk] + mgb[kk], bib[kk], invs);
                if (k == 0) xNyq = Xm;
                else X[kk] = Xm;
            }
            X[k] = Xk;
        }
    }
    __syncthreads();

    // repack X(bufA) -> G(bufB)
    {
        float2* X = bufA;
        float2* G = bufB;
        for (int j = tid; j <= 512; j += 256) {
            float2 Xa = X[j];
            float2 Xb = (j == 0) ? xNyq : X[1024 - j];
            {
                float2 S = make_float2(Xa.x + Xb.x, Xa.y - Xb.y);
                float2 Dd = make_float2(Xa.x - Xb.x, Xa.y + Xb.y);
                float2 wc = make_float2(tws[j].x, -tws[j].y);
                float2 t = cmul(wc, Dd);
                G[j] = make_float2(S.x - t.y, S.y + t.x);
            }
            if (j > 0 && j < 512) {
                int jj = 1024 - j;
                float2 S = make_float2(Xb.x + Xa.x, Xb.y - Xa.y);
                float2 Dd = make_float2(Xb.x - Xa.x, Xb.y + Xa.y);
                float2 wc = make_float2(tws[jj].x, -tws[jj].y);
                float2 t = cmul(wc, Dd);
                G[jj] = make_float2(S.x - t.y, S.y + t.x);
            }
        }
    }
    __syncthreads();

    fft1024<true>(bufB, bufA, tws, tid);  // inverse: result in bufA

    // fuse + contiguous write back into g_xT
    {
        float fw0 = fusion_w[0];
        float fw1 = fusion_w[1];
        float2* orow2 = (float2*)row;
        for (int m = tid; m < 1024; m += 256) {
            float2 zc = bufA[m];
            int p = PADI(2 * m);
            orow2[m] = make_float2(fw0 * (zc.x * invs) + fw1 * s_xl[p],
                                   fw0 * (zc.y * invs) + fw1 * s_xl[p + 1]);
        }
    }
}

// ---------------- fused transpose-out + residual + layernorm ----------------
__global__ __launch_bounds__(256) void ln_fused_kernel(const float* __restrict__ x,
                                                       const float* __restrict__ gamma,
                                                       const float* __restrict__ beta,
                                                       float* __restrict__ out) {
    __shared__ float tile[DD * 9];   // [d][j], row stride 9 (pad) = 27.6KB
    int n0 = blockIdx.x * 8;
    int b = blockIdx.y;
    int tid = threadIdx.x;

    // load 768 x 8 tile of g_xT (fused output, (B,D,N) layout)
    const float* gx = g_xT + (size_t)b * DD * NN + n0;
    for (int idx = tid; idx < DD * 8; idx += 256) {
        int d = idx >> 3;
        int j = idx & 7;
        tile[d * 9 + j] = gx[(size_t)d * NN + j];
    }
    __syncthreads();

    int w = tid >> 5;        // warp -> n offset
    int lane = tid & 31;
    int n = n0 + w;
    const float* xr = x + ((size_t)b * NN + n) * DD;
    float* orow = out + ((size_t)b * NN + n) * DD;

    float y[24];
    float sum = 0.f;
#pragma unroll
    for (int i = 0; i < 24; i++) {
        int d = i * 32 + lane;
        float v = xr[d] + tile[d * 9 + w];
        y[i] = v;
        sum += v;
    }
#pragma unroll
    for (int o = 16; o > 0; o >>= 1) sum += __shfl_xor_sync(0xffffffffu, sum, o);
    float mu = sum * (1.0f / (float)DD);
    float vs = 0.f;
#pragma unroll
    for (int i = 0; i < 24; i++) {
        float d0 = y[i] - mu;
        y[i] = d0;
        vs += d0 * d0;
    }
#pragma unroll
    for (int o = 16; o > 0; o >>= 1) vs += __shfl_xor_sync(0xffffffffu, vs, o);
    float rstd = rsqrtf(vs * (1.0f / (float)DD) + 1e-5f);
#pragma unroll
    for (int i = 0; i < 24; i++) {
        int d = i * 32 + lane;
        orow[d] = y[i] * rstd * gamma[d] + beta[d];
    }
}

// ---------------- launch ----------------
extern "C" void kernel_launch(void* const* d_in, const int* in_sizes, int n_in,
                              void* d_out, int out_size) {
    const float* x = (const float*)d_in[0];
    const float* bf_g = (const float*)d_in[1];
    const float* bf_l = (const float*)d_in[2];
    const float* mb_g = (const float*)d_in[3];
    const float* mb_l = (const float*)d_in[4];
    const float* w1g = (const float*)d_in[5];
    const float* b1g = (const float*)d_in[6];
    const float* w2g = (const float*)d_in[7];
    const float* b2g = (const float*)d_in[8];
    const float* w1l = (const float*)d_in[9];
    const float* b1l = (const float*)d_in[10];
    const float* w2l = (const float*)d_in[11];
    const float* b2l = (const float*)d_in[12];
    const float* fw = (const float*)d_in[13];
    const float* gamma = (const float*)d_in[14];
    const float* beta = (const float*)d_in[15];
    float* out = (float*)d_out;

    init_kernel<<<5, 256>>>();
    tr_in_kernel<<<dim3(24, 64, 8), dim3(32, 8)>>>(x);
    ctx_fin_kernel<<<24, 256>>>();
    mlp1_part_kernel<<<dim3(72, 8, 2), 128>>>(w1g, w1l);
    mlp1_fin_kernel<<<dim3(6, 8, 2), 128>>>(b1g, b1l);
    mlp2_part_kernel<<<dim3(98, 8), 128>>>(w2g, w2l);
    mlp2_fin_kernel<<<dim3(98, 8), 128>>>(b2g, b2l);
    spectral_kernel<<<BD * DD, 256>>>(bf_g, bf_l, mb_g, mb_l, fw);
    ln_fused_kernel<<<dim3(256, 8), 256>>>(x, gamma, beta, out);
}